// round 1
// baseline (speedup 1.0000x reference)
#include <cuda_runtime.h>

#define NTOT 12544   // 16 * 784 flattened spatial*batch
#define HWSZ 784
#define WD   28

// ---------------- scratch (device globals; no allocation allowed) ----------
__device__ float g_xT  [512 * NTOT];   // x transposed to [c][n]
__device__ float g_A   [512 * NTOT];   // t1 (128 rows) then t3 (512 rows)
__device__ float g_B   [128 * NTOT];   // u1 then u2
__device__ float g_C   [128 * NTOT];   // t2
__device__ float g_q1T [512 * 128];    // quantized w1s, k-major [c][p]
__device__ float g_w1aT[128 * 128];    // w1a k-major [c][o]
__device__ float g_q2T [1152 * 128];   // quantized w2s, k-major [(c*9+r*3+s)][p]
__device__ float g_w2aT[1152 * 128];
__device__ float g_q3T [128 * 512];
__device__ float g_w3aT[512 * 512];

template<int ID>
__device__ __forceinline__ float* gbuf(float* rt) {
    if constexpr (ID == 0) return g_xT;
    else if constexpr (ID == 1) return g_A;
    else if constexpr (ID == 2) return g_B;
    else if constexpr (ID == 3) return g_C;
    else if constexpr (ID == 4) return g_q1T;
    else if constexpr (ID == 5) return g_w1aT;
    else if constexpr (ID == 6) return g_q2T;
    else if constexpr (ID == 7) return g_w2aT;
    else if constexpr (ID == 8) return g_q3T;
    else if constexpr (ID == 9) return g_w3aT;
    else return rt;
}

// -------- weight prep: optional power-of-2 quantize + transpose to k-major --
template<int DST, int QUANT>
__global__ void wprep(const float* __restrict__ src, int M, int K) {
    int i = blockIdx.x * blockDim.x + threadIdx.x;
    if (i >= M * K) return;
    float* dst = gbuf<DST>(nullptr);
    int m = i / K, k = i - m * K;
    float w = src[i];
    float q = w;
    if (QUANT) {
        float a = fabsf(w) + 1e-8f;
        q = copysignf(exp2f(rintf(log2f(a))), w);
        if (w == 0.0f) q = 0.0f;   // jnp.sign(0) == 0
    }
    dst[k * M + m] = q;
}

// -------- x: NCHW -> [c][b*784+hw] ----------------------------------------
__global__ void transpose_x(const float* __restrict__ x) {
    int i = blockIdx.x * blockDim.x + threadIdx.x;   // float4 index
    if (i >= 512 * (NTOT / 4)) return;
    int c  = i / (NTOT / 4);
    int r  = i - c * (NTOT / 4);
    int n  = r * 4;
    int b  = n / HWSZ;
    int hw = n - b * HWSZ;
    float4 v = ((const float4*)x)[((b * 512 + c) * HWSZ + hw) >> 2];
    ((float4*)g_xT)[i] = v;
}

// ---------------------------------------------------------------------------
// Unified GEMM-shaped kernel.
//   MODE 0: acc += a*b (shift conv, weights pre-quantized)
//   MODE 1: acc += |b-a| (adder conv; epilogue negates)
//   CONV 0: B operand is X[k][n] (1x1).  CONV 1: implicit 3x3 with zero halo.
//   EPI  0: plain store to Y[m][n]
//   EPI  1: y = relu(inv*(-/+)acc + bias), store to Y[m][n]
//   EPI  2: y = relu(inv*(-acc) + bias + resid), store NCHW to Y
// Operands selected at compile time via buffer IDs (ID<0 -> runtime pointer).
// ---------------------------------------------------------------------------
template<int BM, int BN, int BK, int MODE, int CONV, int EPI,
         int WID, int XID, int YID>
__global__ void __launch_bounds__((BM/8)*(BN/8))
gx(const float* __restrict__ Wrt, const float* __restrict__ Xrt, float* Yrt,
   int Mtot, int K,
   const float* __restrict__ bg, const float* __restrict__ bb,
   const float* __restrict__ bm, const float* __restrict__ bv,
   const float* __restrict__ resid)
{
    constexpr int NT = (BM/8)*(BN/8);
    const float* Wt = gbuf<WID>((float*)Wrt);
    const float* X  = gbuf<XID>((float*)Xrt);
    float*       Y  = gbuf<YID>(Yrt);

    __shared__ float As[BK * BM];
    __shared__ float Bs[BK * BN];

    int tid = threadIdx.x;
    int tx  = tid % (BN/8);
    int ty  = tid / (BN/8);
    int m0  = blockIdx.y * BM;
    int n0  = blockIdx.x * BN;

    float acc[8][8];
#pragma unroll
    for (int i = 0; i < 8; i++)
#pragma unroll
        for (int j = 0; j < 8; j++) acc[i][j] = 0.0f;

    for (int k0 = 0; k0 < K; k0 += BK) {
        // ---- A tile: Wt[k][m], k-major -> As[kk][m] (conflict-free) ----
        for (int v = tid; v < BK * BM / 4; v += NT) {
            int kk = v / (BM/4);
            int mq = v - kk * (BM/4);
            *(float4*)&As[kk * BM + mq * 4] =
                *(const float4*)&Wt[(k0 + kk) * Mtot + m0 + mq * 4];
        }
        // ---- B tile ----
        if (CONV == 0) {
            for (int v = tid; v < BK * BN / 4; v += NT) {
                int kk = v / (BN/4);
                int nq = v - kk * (BN/4);
                *(float4*)&Bs[kk * BN + nq * 4] =
                    *(const float4*)&X[(k0 + kk) * NTOT + n0 + nq * 4];
            }
        } else {
            for (int v = tid; v < BK * BN; v += NT) {
                int kk = v / BN;
                int nn = v - kk * BN;
                int k  = k0 + kk;
                int c  = k / 9;
                int rs = k - c * 9;
                int r  = rs / 3;
                int s  = rs - r * 3;
                int n  = n0 + nn;
                int w  = n % WD;
                int h  = (n / WD) % WD;
                int hh = h + r - 1;
                int ww = w + s - 1;
                float val = 0.0f;
                if (hh >= 0 && hh < WD && ww >= 0 && ww < WD)
                    val = X[c * NTOT + n + (r - 1) * WD + (s - 1)];
                Bs[kk * BN + nn] = val;
            }
        }
        __syncthreads();

#pragma unroll
        for (int kk = 0; kk < BK; kk++) {
            float a[8], b[8];
            *(float4*)&a[0] = *(const float4*)&As[kk * BM + ty * 8];
            *(float4*)&a[4] = *(const float4*)&As[kk * BM + ty * 8 + 4];
            *(float4*)&b[0] = *(const float4*)&Bs[kk * BN + tx * 8];
            *(float4*)&b[4] = *(const float4*)&Bs[kk * BN + tx * 8 + 4];
#pragma unroll
            for (int i = 0; i < 8; i++)
#pragma unroll
                for (int j = 0; j < 8; j++) {
                    if (MODE == 0) acc[i][j] += a[i] * b[j];
                    else           acc[i][j] += fabsf(b[j] - a[i]);
                }
        }
        __syncthreads();
    }

    // ---- epilogue ----
#pragma unroll
    for (int i = 0; i < 8; i++) {
        int m = m0 + ty * 8 + i;
        float inv = 1.0f, bias = 0.0f;
        if (EPI >= 1) {
            inv  = bg[m] * rsqrtf(bv[m] + 1e-5f);
            bias = bb[m] - bm[m] * inv;
        }
        if (EPI == 2) {
#pragma unroll
            for (int j = 0; j < 8; j++) {
                int n   = n0 + tx * 8 + j;
                int b_  = n / HWSZ;
                int hw  = n - b_ * HWSZ;
                int idx = (b_ * 512 + m) * HWSZ + hw;
                float v = -acc[i][j];
                v = v * inv + bias + resid[idx];
                Y[idx] = fmaxf(v, 0.0f);
            }
        } else {
            float o[8];
#pragma unroll
            for (int j = 0; j < 8; j++) {
                float v = (MODE == 0) ? acc[i][j] : -acc[i][j];
                if (EPI == 1) v = fmaxf(v * inv + bias, 0.0f);
                o[j] = v;
            }
            int base = m * NTOT + n0 + tx * 8;
            *(float4*)&Y[base]     = make_float4(o[0], o[1], o[2], o[3]);
            *(float4*)&Y[base + 4] = make_float4(o[4], o[5], o[6], o[7]);
        }
    }
}

// ---------------------------------------------------------------------------
extern "C" void kernel_launch(void* const* d_in, const int* in_sizes, int n_in,
                              void* d_out, int out_size) {
    const float* x   = (const float*)d_in[0];
    const float* w1s = (const float*)d_in[1];
    const float* w1a = (const float*)d_in[2];
    const float* w2s = (const float*)d_in[3];
    const float* w2a = (const float*)d_in[4];
    const float* w3s = (const float*)d_in[5];
    const float* w3a = (const float*)d_in[6];
    const float* g1 = (const float*)d_in[7],  *b1 = (const float*)d_in[8];
    const float* m1 = (const float*)d_in[9],  *v1 = (const float*)d_in[10];
    const float* g2 = (const float*)d_in[11], *b2 = (const float*)d_in[12];
    const float* m2 = (const float*)d_in[13], *v2 = (const float*)d_in[14];
    const float* g3 = (const float*)d_in[15], *b3 = (const float*)d_in[16];
    const float* m3 = (const float*)d_in[17], *v3 = (const float*)d_in[18];
    float* out = (float*)d_out;

    // weight prep (quantize shift weights, transpose all to k-major)
    wprep<4,1><<<(128*512  + 255)/256, 256>>>(w1s, 128, 512);
    wprep<5,0><<<(128*128  + 255)/256, 256>>>(w1a, 128, 128);
    wprep<6,1><<<(128*1152 + 255)/256, 256>>>(w2s, 128, 1152);
    wprep<7,0><<<(128*1152 + 255)/256, 256>>>(w2a, 128, 1152);
    wprep<8,1><<<(512*128  + 255)/256, 256>>>(w3s, 512, 128);
    wprep<9,0><<<(512*512  + 255)/256, 256>>>(w3a, 512, 512);

    // x -> [c][n]
    transpose_x<<<(512*(NTOT/4) + 255)/256, 256>>>(x);

    // stage 1: shift 1x1 (K=512) -> t1 (g_A), adder 1x1 + BN1 + ReLU -> u1 (g_B)
    gx<64,128,32, 0,0,0, 4,0,1><<<dim3(98,2), 128>>>(
        nullptr, nullptr, nullptr, 128, 512,
        nullptr, nullptr, nullptr, nullptr, nullptr);
    gx<64,128,32, 1,0,1, 5,1,2><<<dim3(98,2), 128>>>(
        nullptr, nullptr, nullptr, 128, 128, g1, b1, m1, v1, nullptr);

    // stage 2: shift 3x3 (K=1152) -> t2 (g_C), adder 3x3 + BN2 + ReLU -> u2 (g_B)
    gx<64,128,36, 0,1,0, 6,2,3><<<dim3(98,2), 128>>>(
        nullptr, nullptr, nullptr, 128, 1152,
        nullptr, nullptr, nullptr, nullptr, nullptr);
    gx<64,128,36, 1,1,1, 7,3,2><<<dim3(98,2), 128>>>(
        nullptr, nullptr, nullptr, 128, 1152, g2, b2, m2, v2, nullptr);

    // stage 3: shift 1x1 (M=512,K=128) -> t3 (g_A), adder 1x1 + BN3 + resid + ReLU -> out
    gx<128,128,32, 0,0,0, 8,2,1><<<dim3(98,4), 256>>>(
        nullptr, nullptr, nullptr, 512, 128,
        nullptr, nullptr, nullptr, nullptr, nullptr);
    gx<128,128,32, 1,0,2, 9,1,-1><<<dim3(98,4), 256>>>(
        nullptr, nullptr, out, 512, 512, g3, b3, m3, v3, x);
}

// round 2
// speedup vs baseline: 1.1725x; 1.1725x over previous
#include <cuda_runtime.h>

#define NTOT 12544   // 16 * 784 flattened spatial*batch
#define HWSZ 784
#define WD   28

// ---------------- scratch (device globals; no allocation allowed) ----------
__device__ float g_xT  [512 * NTOT];   // x transposed to [c][n]
__device__ float g_A   [512 * NTOT];   // t1 (128 rows) then t3 (512 rows)
__device__ float g_B   [128 * NTOT];   // u1 then u2
__device__ float g_C   [128 * NTOT];   // t2
__device__ float g_q1T [512 * 128];    // quantized w1s, k-major [c][p]
__device__ float g_w1aT[128 * 128];    // w1a k-major, NEGATED [c][o]
__device__ float g_q2T [1152 * 128];   // quantized w2s, k-major
__device__ float g_w2aT[1152 * 128];   // negated
__device__ float g_q3T [128 * 512];
__device__ float g_w3aT[512 * 512];    // negated

template<int ID>
__device__ __forceinline__ float* gbuf(float* rt) {
    if constexpr (ID == 0) return g_xT;
    else if constexpr (ID == 1) return g_A;
    else if constexpr (ID == 2) return g_B;
    else if constexpr (ID == 3) return g_C;
    else if constexpr (ID == 4) return g_q1T;
    else if constexpr (ID == 5) return g_w1aT;
    else if constexpr (ID == 6) return g_q2T;
    else if constexpr (ID == 7) return g_w2aT;
    else if constexpr (ID == 8) return g_q3T;
    else if constexpr (ID == 9) return g_w3aT;
    else return rt;
}

// -------- weight prep: optional pow2 quantize, optional negate, transpose --
template<int DST, int QUANT, int NEG>
__global__ void wprep(const float* __restrict__ src, int M, int K) {
    int i = blockIdx.x * blockDim.x + threadIdx.x;
    if (i >= M * K) return;
    float* dst = gbuf<DST>(nullptr);
    int m = i / K, k = i - m * K;
    float w = src[i];
    float q = w;
    if (QUANT) {
        float a = fabsf(w) + 1e-8f;
        q = copysignf(exp2f(rintf(log2f(a))), w);
        if (w == 0.0f) q = 0.0f;   // jnp.sign(0) == 0
    }
    if (NEG) q = -q;
    dst[k * M + m] = q;
}

// -------- x: NCHW -> [c][b*784+hw] ----------------------------------------
__global__ void transpose_x(const float* __restrict__ x) {
    int i = blockIdx.x * blockDim.x + threadIdx.x;   // float4 index
    if (i >= 512 * (NTOT / 4)) return;
    int c  = i / (NTOT / 4);
    int r  = i - c * (NTOT / 4);
    int n  = r * 4;
    int b  = n / HWSZ;
    int hw = n - b * HWSZ;
    float4 v = ((const float4*)x)[((b * 512 + c) * HWSZ + hw) >> 2];
    ((float4*)g_xT)[i] = v;
}

// ---------------------------------------------------------------------------
// Unified GEMM-shaped kernel, packed-f32x2 inner loop.
//   MODE 0: acc += a*b (shift conv; A holds quantized weights)
//   MODE 1: acc += |b-a| (adder; A holds NEGATED weights; epilogue negates sum)
//   CONV 0: B operand is X[k][n] (1x1).  CONV 1: implicit 3x3 with zero halo.
//   EPI 0: plain store  EPI 1: relu(bn)  EPI 2: relu(bn + resid), NCHW store
// ---------------------------------------------------------------------------
template<int BM, int BN, int BK, int MODE, int CONV, int EPI,
         int WID, int XID, int YID>
__global__ void __launch_bounds__((BM/8)*(BN/8))
gx(const float* __restrict__ Wrt, const float* __restrict__ Xrt, float* Yrt,
   int Mtot, int K,
   const float* __restrict__ bg, const float* __restrict__ bb,
   const float* __restrict__ bm, const float* __restrict__ bv,
   const float* __restrict__ resid)
{
    constexpr int NT = (BM/8)*(BN/8);
    static_assert(CONV == 0 || NT == BN, "conv fill assumes one thread per column");
    const float* Wt = gbuf<WID>((float*)Wrt);
    const float* X  = gbuf<XID>((float*)Xrt);
    float*       Y  = gbuf<YID>(Yrt);

    __shared__ __align__(16) float As[BK * BM];
    __shared__ __align__(16) float Bs[BK * BN];

    int tid = threadIdx.x;
    int tx  = tid % (BN/8);
    int ty  = tid / (BN/8);
    int m0  = blockIdx.y * BM;
    int n0  = blockIdx.x * BN;

    // per-thread conv geometry (column n fixed for the whole kernel)
    int ch = 0, cw = 0;
    if (CONV == 1) {
        int n = n0 + tid;
        cw = n % WD;
        ch = (n / WD) % WD;
    }

    unsigned long long acc2[8][4];
#pragma unroll
    for (int i = 0; i < 8; i++)
#pragma unroll
        for (int j = 0; j < 4; j++) acc2[i][j] = 0ULL;

    for (int k0 = 0; k0 < K; k0 += BK) {
        // ---- A tile: Wt[k][m], k-major -> As[kk][m] ----
        for (int v = tid; v < BK * BM / 4; v += NT) {
            int kk = v / (BM/4);
            int mq = v - kk * (BM/4);
            *(float4*)&As[kk * BM + mq * 4] =
                *(const float4*)&Wt[(k0 + kk) * Mtot + m0 + mq * 4];
        }
        // ---- B tile ----
        if (CONV == 0) {
            for (int v = tid; v < BK * BN / 4; v += NT) {
                int kk = v / (BN/4);
                int nq = v - kk * (BN/4);
                *(float4*)&Bs[kk * BN + nq * 4] =
                    *(const float4*)&X[(k0 + kk) * NTOT + n0 + nq * 4];
            }
        } else {
            // one thread per column; kk/9, kk%9 constant-folded by unroll
            int cbase = k0 / 9;          // BK=36 => k0 multiple of 9
            int n = n0 + tid;
#pragma unroll
            for (int kk = 0; kk < BK; kk++) {
                const int r = (kk % 9) / 3;
                const int s = (kk % 9) % 3;
                int c  = cbase + kk / 9;
                int hh = ch + r - 1;
                int ww = cw + s - 1;
                float val = 0.0f;
                if (hh >= 0 && hh < WD && ww >= 0 && ww < WD)
                    val = X[c * NTOT + n + (r - 1) * WD + (s - 1)];
                Bs[kk * BN + tid] = val;
            }
        }
        __syncthreads();

#pragma unroll 4
        for (int kk = 0; kk < BK; kk++) {
            float a[8];
            *(float4*)&a[0] = *(const float4*)&As[kk * BM + ty * 8];
            *(float4*)&a[4] = *(const float4*)&As[kk * BM + ty * 8 + 4];
            unsigned long long ad[8];
#pragma unroll
            for (int i = 0; i < 8; i++)
                asm("mov.b64 %0, {%1, %1};" : "=l"(ad[i]) : "f"(a[i]));
            unsigned long long b2[4];
            {
                ulonglong2 p0 = *(const ulonglong2*)&Bs[kk * BN + tx * 8];
                ulonglong2 p1 = *(const ulonglong2*)&Bs[kk * BN + tx * 8 + 4];
                b2[0] = p0.x; b2[1] = p0.y; b2[2] = p1.x; b2[3] = p1.y;
            }
#pragma unroll
            for (int i = 0; i < 8; i++)
#pragma unroll
                for (int jp = 0; jp < 4; jp++) {
                    if (MODE == 0) {
                        // acc2 += a_dup * b2   (FFMA2, fma pipe)
                        asm("fma.rn.f32x2 %0, %1, %2, %0;"
                            : "+l"(acc2[i][jp]) : "l"(ad[i]), "l"(b2[jp]));
                    } else {
                        // t = b - a  (ad holds -a);  t = |t| (2x LOP3, alu pipe)
                        unsigned long long t;
                        asm("add.rn.f32x2 %0, %1, %2;"
                            : "=l"(t) : "l"(b2[jp]), "l"(ad[i]));
                        t &= 0x7FFFFFFF7FFFFFFFULL;
                        asm("add.rn.f32x2 %0, %0, %1;"
                            : "+l"(acc2[i][jp]) : "l"(t));
                    }
                }
        }
        __syncthreads();
    }

    // ---- unpack ----
    float accf[8][8];
#pragma unroll
    for (int i = 0; i < 8; i++)
#pragma unroll
        for (int jp = 0; jp < 4; jp++)
            asm("mov.b64 {%0, %1}, %2;"
                : "=f"(accf[i][2*jp]), "=f"(accf[i][2*jp+1]) : "l"(acc2[i][jp]));

    // ---- epilogue ----
#pragma unroll
    for (int i = 0; i < 8; i++) {
        int m = m0 + ty * 8 + i;
        float inv = 1.0f, bias = 0.0f;
        if (EPI >= 1) {
            inv  = bg[m] * rsqrtf(bv[m] + 1e-5f);
            bias = bb[m] - bm[m] * inv;
        }
        if (EPI == 2) {
#pragma unroll
            for (int j = 0; j < 8; j++) {
                int n   = n0 + tx * 8 + j;
                int b_  = n / HWSZ;
                int hw  = n - b_ * HWSZ;
                int idx = (b_ * 512 + m) * HWSZ + hw;
                float v = -accf[i][j];
                v = v * inv + bias + resid[idx];
                Y[idx] = fmaxf(v, 0.0f);
            }
        } else {
            float o[8];
#pragma unroll
            for (int j = 0; j < 8; j++) {
                float v = (MODE == 0) ? accf[i][j] : -accf[i][j];
                if (EPI == 1) v = fmaxf(v * inv + bias, 0.0f);
                o[j] = v;
            }
            int base = m * NTOT + n0 + tx * 8;
            *(float4*)&Y[base]     = make_float4(o[0], o[1], o[2], o[3]);
            *(float4*)&Y[base + 4] = make_float4(o[4], o[5], o[6], o[7]);
        }
    }
}

// ---------------------------------------------------------------------------
extern "C" void kernel_launch(void* const* d_in, const int* in_sizes, int n_in,
                              void* d_out, int out_size) {
    const float* x   = (const float*)d_in[0];
    const float* w1s = (const float*)d_in[1];
    const float* w1a = (const float*)d_in[2];
    const float* w2s = (const float*)d_in[3];
    const float* w2a = (const float*)d_in[4];
    const float* w3s = (const float*)d_in[5];
    const float* w3a = (const float*)d_in[6];
    const float* g1 = (const float*)d_in[7],  *b1 = (const float*)d_in[8];
    const float* m1 = (const float*)d_in[9],  *v1 = (const float*)d_in[10];
    const float* g2 = (const float*)d_in[11], *b2 = (const float*)d_in[12];
    const float* m2 = (const float*)d_in[13], *v2 = (const float*)d_in[14];
    const float* g3 = (const float*)d_in[15], *b3 = (const float*)d_in[16];
    const float* m3 = (const float*)d_in[17], *v3 = (const float*)d_in[18];
    float* out = (float*)d_out;

    // weight prep: quantize shift weights; NEGATE adder weights; all k-major
    wprep<4,1,0><<<(128*512  + 255)/256, 256>>>(w1s, 128, 512);
    wprep<5,0,1><<<(128*128  + 255)/256, 256>>>(w1a, 128, 128);
    wprep<6,1,0><<<(128*1152 + 255)/256, 256>>>(w2s, 128, 1152);
    wprep<7,0,1><<<(128*1152 + 255)/256, 256>>>(w2a, 128, 1152);
    wprep<8,1,0><<<(512*128  + 255)/256, 256>>>(w3s, 512, 128);
    wprep<9,0,1><<<(512*512  + 255)/256, 256>>>(w3a, 512, 512);

    // x -> [c][n]
    transpose_x<<<(512*(NTOT/4) + 255)/256, 256>>>(x);

    // stage 1: shift 1x1 (K=512) -> t1 (g_A); adder 1x1 + BN1 + ReLU -> u1 (g_B)
    gx<64,128,32, 0,0,0, 4,0,1><<<dim3(98,2), 128>>>(
        nullptr, nullptr, nullptr, 128, 512,
        nullptr, nullptr, nullptr, nullptr, nullptr);
    gx<64,128,32, 1,0,1, 5,1,2><<<dim3(98,2), 128>>>(
        nullptr, nullptr, nullptr, 128, 128, g1, b1, m1, v1, nullptr);

    // stage 2: shift 3x3 (K=1152) -> t2 (g_C); adder 3x3 + BN2 + ReLU -> u2 (g_B)
    gx<64,128,36, 0,1,0, 6,2,3><<<dim3(98,2), 128>>>(
        nullptr, nullptr, nullptr, 128, 1152,
        nullptr, nullptr, nullptr, nullptr, nullptr);
    gx<64,128,36, 1,1,1, 7,3,2><<<dim3(98,2), 128>>>(
        nullptr, nullptr, nullptr, 128, 1152, g2, b2, m2, v2, nullptr);

    // stage 3: shift 1x1 (M=512,K=128) -> t3 (g_A); adder 1x1 + BN3 + resid + ReLU -> out
    gx<128,128,32, 0,0,0, 8,2,1><<<dim3(98,4), 256>>>(
        nullptr, nullptr, nullptr, 512, 128,
        nullptr, nullptr, nullptr, nullptr, nullptr);
    gx<128,128,32, 1,0,2, 9,1,-1><<<dim3(98,4), 256>>>(
        nullptr, nullptr, out, 512, 512, g3, b3, m3, v3, x);
}